// round 3
// baseline (speedup 1.0000x reference)
#include <cuda_runtime.h>

#define NN 50000
#define DD 64
#define HH 128
#define EE 500000
#define ZSZ (NN*DD)

typedef unsigned long long ull;

// ---------------------------------------------------------------- scratch
__device__ float g_z[(size_t)8*ZSZ];   // 0-3 GAT planes, 4-7 GC planes
__device__ float g_s[4*NN];            // GAT softmax denominators
__device__ float g_el[4*NN];
__device__ float g_er[4*NN];
__device__ float g_no[4*NN];           // GC out-deg -> rsqrt
__device__ float g_ni[4*NN];           // GC in-deg  -> rsqrt
__device__ float g_wsum[8];
__device__ float g_beta[8];

struct G4 { const int* s[4]; const int* d[4]; const float* f[4]; };
struct SaP { const float* W1[4]; const float* b1[4]; const float* w2[4]; };

// ---------------------------------------------------------------- utils
__device__ __forceinline__ ull pack2(float a, float b) {
    ull r; asm("mov.b64 %0, {%1,%2};" : "=l"(r) : "f"(a), "f"(b)); return r;
}
__device__ __forceinline__ void unpack2(ull v, float& a, float& b) {
    asm("mov.b64 {%0,%1}, %2;" : "=f"(a), "=f"(b) : "l"(v));
}
__device__ __forceinline__ ull ffma2(ull a, ull b, ull c) {
    ull d; asm("fma.rn.f32x2 %0, %1, %2, %3;" : "=l"(d) : "l"(a), "l"(b), "l"(c));
    return d;
}
__device__ __forceinline__ float tanha(float x) {
    float r; asm("tanh.approx.f32 %0, %1;" : "=f"(r) : "f"(x)); return r;
}
__device__ __forceinline__ float elu(float x) { return x > 0.f ? x : expm1f(x); }

// ---------------------------------------------------------------- zero
__global__ void zero_k() {
    int t = blockIdx.x * blockDim.x + threadIdx.x;
    ((float4*)g_z)[t] = make_float4(0.f,0.f,0.f,0.f);  // grid covers 8*ZSZ/4 exactly
    if (t < 4*NN) { g_s[t] = 0.f; g_no[t] = 0.f; g_ni[t] = 0.f; }
    if (t < 8) g_wsum[t] = 0.f;
}

// -------------------------------------- fused el/er for all 4 GAT relations
// y=0: user table (er for g0,g1 ; el for g2,g3) ; y=1: item table (el g0,g1 ; er g2,g3)
__global__ void ler_all_k(const float* __restrict__ feat_user,
                          const float* __restrict__ feat_item,
                          const float* __restrict__ attn_l,
                          const float* __restrict__ attn_r) {
    int tbl = blockIdx.y;
    int w = (blockIdx.x * blockDim.x + threadIdx.x) >> 5;
    int lane = threadIdx.x & 31;
    const float* f = (tbl == 0 ? feat_user : feat_item) + (size_t)w * DD;
    float f0 = f[lane], f1 = f[lane + 32];
    const float* v0; const float* v1; const float* v2; const float* v3;
    if (tbl == 0) { v0 = attn_r; v1 = attn_r + DD; v2 = attn_l + 2*DD; v3 = attn_l + 3*DD; }
    else          { v0 = attn_l; v1 = attn_l + DD; v2 = attn_r + 2*DD; v3 = attn_r + 3*DD; }
    float s0 = f0*__ldg(v0+lane) + f1*__ldg(v0+lane+32);
    float s1 = f0*__ldg(v1+lane) + f1*__ldg(v1+lane+32);
    float s2 = f0*__ldg(v2+lane) + f1*__ldg(v2+lane+32);
    float s3 = f0*__ldg(v3+lane) + f1*__ldg(v3+lane+32);
    #pragma unroll
    for (int o = 16; o; o >>= 1) {
        s0 += __shfl_down_sync(0xffffffffu, s0, o);
        s1 += __shfl_down_sync(0xffffffffu, s1, o);
        s2 += __shfl_down_sync(0xffffffffu, s2, o);
        s3 += __shfl_down_sync(0xffffffffu, s3, o);
    }
    if (lane == 0) {
        if (tbl == 0) { g_er[w] = s0; g_er[NN+w] = s1; g_el[2*NN+w] = s2; g_el[3*NN+w] = s3; }
        else          { g_el[w] = s0; g_el[NN+w] = s1; g_er[2*NN+w] = s2; g_er[3*NN+w] = s3; }
    }
}

// ---------------------------------------------------------------- GAT scatter
__global__ void gat_scatter_k(G4 G) {
    int g = blockIdx.y;
    int t = blockIdx.x * blockDim.x + threadIdx.x;
    int edge = t >> 4;
    int sub  = t & 15;
    int si = __ldg(G.s[g] + edge);
    int di = __ldg(G.d[g] + edge);
    float e = g_el[g*NN + si] + g_er[g*NN + di];
    e = e > 0.f ? e : 0.01f * e;
    float ex = __expf(e);
    if (sub == 0) atomicAdd(g_s + g*NN + di, ex);
    float4 f = __ldg((const float4*)G.f[g] + (size_t)si * 16 + sub);
    float* zp = g_z + (size_t)g*ZSZ + (size_t)di*DD + sub*4;
    asm volatile("red.global.add.v4.f32 [%0], {%1, %2, %3, %4};"
                 :: "l"(zp), "f"(ex*f.x), "f"(ex*f.y), "f"(ex*f.z), "f"(ex*f.w)
                 : "memory");
}

// ---------------------------------------------------------------- GAT final
__global__ void gat_final_k() {
    int g = blockIdx.y;
    int t = blockIdx.x * blockDim.x + threadIdx.x;
    float sv = g_s[g*NN + (t >> 6)];
    float* z = g_z + (size_t)g*ZSZ;
    float v = sv > 0.f ? z[t] / sv : 0.f;
    z[t] = v > 0.f ? v : expm1f(v);
}

// ---------------------------------------------------------------- GC degrees
__global__ void deg_k(G4 C) {
    int g = blockIdx.y;
    int e = blockIdx.x * blockDim.x + threadIdx.x;
    if (e >= EE) return;
    atomicAdd(g_no + g*NN + __ldg(C.s[g] + e), 1.f);
    atomicAdd(g_ni + g*NN + __ldg(C.d[g] + e), 1.f);
}

__global__ void norm_k() {
    int t = blockIdx.x * blockDim.x + threadIdx.x;
    if (t >= 4*NN) return;
    float a = g_no[t]; g_no[t] = rsqrtf(a > 0.f ? a : 1.f);
    float b = g_ni[t]; g_ni[t] = rsqrtf(b > 0.f ? b : 1.f);
}

// ---------------------------------------------------------------- GC scatter
__global__ void gc_scatter_k(G4 C) {
    int g = blockIdx.y;
    int t = blockIdx.x * blockDim.x + threadIdx.x;
    int edge = t >> 4;
    int sub = t & 15;
    int si = __ldg(C.s[g] + edge);
    int di = __ldg(C.d[g] + edge);
    float c = g_no[g*NN + si];
    float4 f = __ldg((const float4*)C.f[g] + (size_t)si * 16 + sub);
    float* zp = g_z + (size_t)(4+g)*ZSZ + (size_t)di*DD + sub*4;
    asm volatile("red.global.add.v4.f32 [%0], {%1, %2, %3, %4};"
                 :: "l"(zp), "f"(c*f.x), "f"(c*f.y), "f"(c*f.z), "f"(c*f.w)
                 : "memory");
}

// ----------------------------------------- GC: ni-scale + 64x64 GEMM + ELU
__global__ void gc_gemm_k(const float* __restrict__ W_gc, const float* __restrict__ b_gc) {
    __shared__ float Wsh[DD*DD];
    int g = blockIdx.y, t = threadIdx.x;
    const float* W = W_gc + g*DD*DD;
    #pragma unroll
    for (int i = t; i < DD*DD; i += 256) Wsh[i] = W[i];
    __syncthreads();
    int node = blockIdx.x * 8 + (t >> 5);
    int lane = t & 31;
    float* z = g_z + (size_t)(4+g)*ZSZ + (size_t)node*DD;
    float c = g_ni[g*NN + node];
    float r0 = z[lane]*c, r1 = z[lane+32]*c;
    const float* b = b_gc + g*DD;
    float a0 = b[lane], a1 = b[lane+32];
    #pragma unroll
    for (int d = 0; d < 32; d++) {
        float v = __shfl_sync(0xffffffffu, r0, d);
        a0 += v*Wsh[d*DD + lane];
        a1 += v*Wsh[d*DD + lane + 32];
    }
    #pragma unroll
    for (int d = 0; d < 32; d++) {
        float v = __shfl_sync(0xffffffffu, r1, d);
        a0 += v*Wsh[(d+32)*DD + lane];
        a1 += v*Wsh[(d+32)*DD + lane + 32];
    }
    z[lane]      = a0 > 0.f ? a0 : expm1f(a0);
    z[lane + 32] = a1 > 0.f ? a1 : expm1f(a1);
}

// ---------------------------------------------------- semantic attention score
// Block: 256 thr = 32 node-groups x 8 h-threads. 128 nodes/block, 2 planes.
// Thread: 8 rows (4 nodes x 2 planes) x 16 h (strided pairs 2hq+16j) via FFMA2.
#define NPB 128
#define ZST 68
__global__ void __launch_bounds__(256) sa_score_k(SaP S) {
    extern __shared__ float sm[];
    float* W1sh = sm;                    // 8192
    float* zsh  = sm + DD*HH;            // 2*128*68
    float* b1sh = zsh + 2*NPB*ZST;       // 128
    float* w2sh = b1sh + HH;             // 128
    float* red  = w2sh + HH;             // 2

    int g = blockIdx.y, t = threadIdx.x;
    for (int i = t; i < DD*HH; i += 256) W1sh[i] = S.W1[g][i];
    if (t < HH) { b1sh[t] = S.b1[g][t]; w2sh[t] = S.w2[g][t]; }
    if (t < 2) red[t] = 0.f;

    int nb = blockIdx.x * NPB;
    const float4* base = (const float4*)(g_z + (size_t)(2*g)*ZSZ);
    for (int idx = t; idx < 2*NPB*16; idx += 256) {
        int p = idx >> 11;
        int n = (idx >> 4) & (NPB-1);
        int v = idx & 15;
        float4 val = make_float4(0.f,0.f,0.f,0.f);
        int gn = nb + n;
        if (gn < NN) val = __ldg(base + (size_t)p*(ZSZ/4) + (size_t)gn*16 + v);
        ((float4*)(zsh + (p*NPB + n)*ZST))[v] = val;
    }
    __syncthreads();

    int ng = t >> 3;      // 0..31
    int hq = t & 7;       // 0..7
    ull acc[8][8];
    #pragma unroll
    for (int j = 0; j < 8; j++) {
        ull b = *(const ull*)(b1sh + 2*hq + 16*j);
        #pragma unroll
        for (int r = 0; r < 8; r++) acc[r][j] = b;
    }

    const float* z0 = zsh + (ng*4)*ZST;
    const float* z1 = zsh + (NPB + ng*4)*ZST;
    for (int d = 0; d < DD; d++) {
        ull zp[8];
        #pragma unroll
        for (int i = 0; i < 4; i++) {
            float a = z0[i*ZST + d]; zp[i]   = pack2(a, a);
            float b = z1[i*ZST + d]; zp[4+i] = pack2(b, b);
        }
        const float* wrow = W1sh + d*HH;
        #pragma unroll
        for (int j = 0; j < 8; j++) {
            ull w = *(const ull*)(wrow + 2*hq + 16*j);
            #pragma unroll
            for (int r = 0; r < 8; r++) acc[r][j] = ffma2(zp[r], w, acc[r][j]);
        }
    }

    float part0 = 0.f, part1 = 0.f;
    #pragma unroll
    for (int r = 0; r < 8; r++) {
        int node = nb + ng*4 + (r & 3);
        if (node >= NN) continue;
        float s = 0.f;
        #pragma unroll
        for (int j = 0; j < 8; j++) {
            float wa = w2sh[2*hq + 16*j], wb = w2sh[2*hq + 16*j + 1];
            float lo, hi; unpack2(acc[r][j], lo, hi);
            s += tanha(lo)*wa + tanha(hi)*wb;
        }
        if (r < 4) part0 += s; else part1 += s;
    }
    #pragma unroll
    for (int o = 16; o; o >>= 1) {
        part0 += __shfl_down_sync(0xffffffffu, part0, o);
        part1 += __shfl_down_sync(0xffffffffu, part1, o);
    }
    if ((t & 31) == 0) { atomicAdd(&red[0], part0); atomicAdd(&red[1], part1); }
    __syncthreads();
    if (t == 0) {
        atomicAdd(g_wsum + 2*g,     red[0]);
        atomicAdd(g_wsum + 2*g + 1, red[1]);
    }
}

// ---------------------------------------------------------------- beta
__global__ void beta_k() {
    #pragma unroll
    for (int g = 0; g < 4; g++) {
        float w0 = g_wsum[2*g]   * (1.0f/NN);
        float w1 = g_wsum[2*g+1] * (1.0f/NN);
        float m = fmaxf(w0, w1);
        float e0 = __expf(w0-m), e1 = __expf(w1-m);
        float inv = 1.f/(e0+e1);
        g_beta[2*g] = e0*inv; g_beta[2*g+1] = e1*inv;
    }
}

// ---------------------------------------------------------------- combine
__global__ void combine_k(float* __restrict__ out) {
    int t = blockIdx.x * blockDim.x + threadIdx.x;
    const float4* Z = (const float4*)g_z;
    const size_t Pp = ZSZ/4;
    float4 r;
    if (t < NN*16) {
        float b0=g_beta[0], b1=g_beta[1], b4=g_beta[4], b5=g_beta[5];
        float4 x0=Z[t], x1=Z[Pp+t], x4=Z[4*Pp+t], x5=Z[5*Pp+t];
        r.x = b0*x0.x+b1*x1.x+b4*x4.x+b5*x5.x;
        r.y = b0*x0.y+b1*x1.y+b4*x4.y+b5*x5.y;
        r.z = b0*x0.z+b1*x1.z+b4*x4.z+b5*x5.z;
        r.w = b0*x0.w+b1*x1.w+b4*x4.w+b5*x5.w;
    } else {
        size_t u = t - NN*16;
        float b2=g_beta[2], b3=g_beta[3], b6=g_beta[6], b7=g_beta[7];
        float4 x2=Z[2*Pp+u], x3=Z[3*Pp+u], x6=Z[6*Pp+u], x7=Z[7*Pp+u];
        r.x = b2*x2.x+b3*x3.x+b6*x6.x+b7*x7.x;
        r.y = b2*x2.y+b3*x3.y+b6*x6.y+b7*x7.y;
        r.z = b2*x2.z+b3*x3.z+b6*x6.z+b7*x7.z;
        r.w = b2*x2.w+b3*x3.w+b6*x6.w+b7*x7.w;
    }
    ((float4*)out)[t] = r;
}

// ============================================================== host launcher
extern "C" void kernel_launch(void* const* d_in, const int* in_sizes, int n_in,
                              void* d_out, int out_size) {
    const float* feat_user = (const float*)d_in[0];
    const float* feat_item = (const float*)d_in[1];
    const float* attn_l    = (const float*)d_in[2];
    const float* attn_r    = (const float*)d_in[3];
    const float* W_gc      = (const float*)d_in[4];
    const float* b_gc      = (const float*)d_in[5];
    const float* sa_rel_W1 = (const float*)d_in[6];
    const float* sa_rel_b1 = (const float*)d_in[7];
    const float* sa_rel_w2 = (const float*)d_in[8];
    const float* sa_u_W1   = (const float*)d_in[9];
    const float* sa_u_b1   = (const float*)d_in[10];
    const float* sa_u_w2   = (const float*)d_in[11];
    const float* sa_i_W1   = (const float*)d_in[12];
    const float* sa_i_b1   = (const float*)d_in[13];
    const float* sa_i_w2   = (const float*)d_in[14];
    const int* rel_u_src   = (const int*)d_in[15];
    const int* rel_u_dst   = (const int*)d_in[16];
    const int* rel_i_src   = (const int*)d_in[17];
    const int* rel_i_dst   = (const int*)d_in[18];
    const int* mp_u_src    = (const int*)d_in[19];
    const int* mp_u_dst    = (const int*)d_in[20];
    const int* mp_i_src    = (const int*)d_in[21];
    const int* mp_i_dst    = (const int*)d_in[22];
    float* out = (float*)d_out;

    G4 G;  // GAT relations (src features)
    G.s[0]=rel_u_src;    G.d[0]=rel_u_dst;    G.f[0]=feat_item;
    G.s[1]=rel_u_src+EE; G.d[1]=rel_u_dst+EE; G.f[1]=feat_item;
    G.s[2]=rel_i_src;    G.d[2]=rel_i_dst;    G.f[2]=feat_user;
    G.s[3]=rel_i_src+EE; G.d[3]=rel_i_dst+EE; G.f[3]=feat_user;
    G4 C;  // GC meta-path graphs
    C.s[0]=mp_u_src;     C.d[0]=mp_u_dst;     C.f[0]=feat_user;
    C.s[1]=mp_u_src+EE;  C.d[1]=mp_u_dst+EE;  C.f[1]=feat_user;
    C.s[2]=mp_i_src;     C.d[2]=mp_i_dst;     C.f[2]=feat_item;
    C.s[3]=mp_i_src+EE;  C.d[3]=mp_i_dst+EE;  C.f[3]=feat_item;
    SaP S;
    S.W1[0]=sa_rel_W1; S.b1[0]=sa_rel_b1; S.w2[0]=sa_rel_w2;
    S.W1[1]=sa_rel_W1; S.b1[1]=sa_rel_b1; S.w2[1]=sa_rel_w2;
    S.W1[2]=sa_u_W1;   S.b1[2]=sa_u_b1;   S.w2[2]=sa_u_w2;
    S.W1[3]=sa_i_W1;   S.b1[3]=sa_i_b1;   S.w2[3]=sa_i_w2;

    const int TB = 256;

    zero_k<<<8*ZSZ/4/TB, TB>>>();                       // 25000 blocks
    ler_all_k<<<dim3(NN*32/TB, 2), TB>>>(feat_user, feat_item, attn_l, attn_r);
    deg_k<<<dim3((EE+TB-1)/TB, 4), TB>>>(C);
    norm_k<<<(4*NN+TB-1)/TB, TB>>>();
    gat_scatter_k<<<dim3(EE*16/TB, 4), TB>>>(G);
    gat_final_k<<<dim3(ZSZ/TB, 4), TB>>>();
    gc_scatter_k<<<dim3(EE*16/TB, 4), TB>>>(C);
    gc_gemm_k<<<dim3(NN/8, 4), TB>>>(W_gc, b_gc);

    int sa_smem = (DD*HH + 2*NPB*ZST + HH + HH + 2) * sizeof(float);
    cudaFuncSetAttribute(sa_score_k, cudaFuncAttributeMaxDynamicSharedMemorySize, sa_smem);
    sa_score_k<<<dim3((NN + NPB - 1)/NPB, 4), TB, sa_smem>>>(S);

    beta_k<<<1, 1>>>();
    combine_k<<<2*NN*16/TB, TB>>>(out);
}

// round 5
// speedup vs baseline: 1.9583x; 1.9583x over previous
#include <cuda_runtime.h>

#define NN 50000
#define DD 64
#define HH 128
#define EE 500000
#define ZSZ (NN*DD)
#define EB 128          // edges per scatter block

typedef unsigned long long ull;

// ---------------------------------------------------------------- scratch
__device__ float g_z[(size_t)8*ZSZ];   // 0-3 GAT planes, 4-7 GC planes
__device__ float g_s[4*NN];            // GAT softmax denominators
__device__ float g_el[4*NN];
__device__ float g_er[4*NN];
__device__ float g_no[4*NN];           // GC out-deg -> rsqrt
__device__ float g_ni[4*NN];           // GC in-deg  -> rsqrt
__device__ float g_wsum[8];
__device__ float g_beta[8];

struct G4 { const int* s[4]; const int* d[4]; };
struct SaP { const float* W1[4]; const float* b1[4]; const float* w2[4]; };

// ---------------------------------------------------------------- utils
__device__ __forceinline__ ull pack2(float a, float b) {
    ull r; asm("mov.b64 %0, {%1,%2};" : "=l"(r) : "f"(a), "f"(b)); return r;
}
__device__ __forceinline__ void unpack2(ull v, float& a, float& b) {
    asm("mov.b64 {%0,%1}, %2;" : "=f"(a), "=f"(b) : "l"(v));
}
__device__ __forceinline__ ull ffma2(ull a, ull b, ull c) {
    ull d; asm("fma.rn.f32x2 %0, %1, %2, %3;" : "=l"(d) : "l"(a), "l"(b), "l"(c));
    return d;
}
__device__ __forceinline__ float tanha(float x) {
    float r; asm("tanh.approx.f32 %0, %1;" : "=f"(r) : "f"(x)); return r;
}
__device__ __forceinline__ void red4(float* p, float a, float b, float c, float d) {
    asm volatile("red.global.add.v4.f32 [%0], {%1, %2, %3, %4};"
                 :: "l"(p), "f"(a), "f"(b), "f"(c), "f"(d));   // no mem clobber: keep MLP
}

// ---------------------------------------------------------------- zero utils
__global__ void zero_nodes_k() {
    int t = blockIdx.x * blockDim.x + threadIdx.x;
    if (t < 4*NN) { g_s[t] = 0.f; g_no[t] = 0.f; g_ni[t] = 0.f; }
    if (t < 8) g_wsum[t] = 0.f;
}

__global__ void zero_plane_k(float* __restrict__ z) {
    int t = blockIdx.x * blockDim.x + threadIdx.x;
    ((float4*)z)[t] = make_float4(0.f,0.f,0.f,0.f);   // grid covers ZSZ/4 exactly
}

// -------------------------------------- fused el/er for all 4 GAT relations
__global__ void ler_all_k(const float* __restrict__ feat_user,
                          const float* __restrict__ feat_item,
                          const float* __restrict__ attn_l,
                          const float* __restrict__ attn_r) {
    int tbl = blockIdx.y;
    int w = (blockIdx.x * blockDim.x + threadIdx.x) >> 5;
    int lane = threadIdx.x & 31;
    const float* f = (tbl == 0 ? feat_user : feat_item) + (size_t)w * DD;
    float f0 = f[lane], f1 = f[lane + 32];
    const float* v0; const float* v1; const float* v2; const float* v3;
    if (tbl == 0) { v0 = attn_r; v1 = attn_r + DD; v2 = attn_l + 2*DD; v3 = attn_l + 3*DD; }
    else          { v0 = attn_l; v1 = attn_l + DD; v2 = attn_r + 2*DD; v3 = attn_r + 3*DD; }
    float s0 = f0*__ldg(v0+lane) + f1*__ldg(v0+lane+32);
    float s1 = f0*__ldg(v1+lane) + f1*__ldg(v1+lane+32);
    float s2 = f0*__ldg(v2+lane) + f1*__ldg(v2+lane+32);
    float s3 = f0*__ldg(v3+lane) + f1*__ldg(v3+lane+32);
    #pragma unroll
    for (int o = 16; o; o >>= 1) {
        s0 += __shfl_down_sync(0xffffffffu, s0, o);
        s1 += __shfl_down_sync(0xffffffffu, s1, o);
        s2 += __shfl_down_sync(0xffffffffu, s2, o);
        s3 += __shfl_down_sync(0xffffffffu, s3, o);
    }
    if (lane == 0) {
        if (tbl == 0) { g_er[w] = s0; g_er[NN+w] = s1; g_el[2*NN+w] = s2; g_el[3*NN+w] = s3; }
        else          { g_el[w] = s0; g_el[NN+w] = s1; g_er[2*NN+w] = s2; g_er[3*NN+w] = s3; }
    }
}

// ---------------------------------------------------------------- GC degrees
__global__ void deg_k(G4 C) {
    int g = blockIdx.y;
    int e = blockIdx.x * blockDim.x + threadIdx.x;
    if (e >= EE) return;
    atomicAdd(g_no + g*NN + __ldg(C.s[g] + e), 1.f);
    atomicAdd(g_ni + g*NN + __ldg(C.d[g] + e), 1.f);
}

__global__ void norm_k() {
    int t = blockIdx.x * blockDim.x + threadIdx.x;
    if (t >= 4*NN) return;
    float a = g_no[t]; g_no[t] = rsqrtf(a > 0.f ? a : 1.f);
    float b = g_ni[t]; g_ni[t] = rsqrtf(b > 0.f ? b : 1.f);
}

// ------------------------------------------------- GAT scatter (smem-staged)
__global__ void __launch_bounds__(256) gat_scatter_k(
        const int* __restrict__ src, const int* __restrict__ dst,
        const float* __restrict__ fsrc,
        const float* __restrict__ el, const float* __restrict__ er,
        float* __restrict__ s, float* __restrict__ z) {
    __shared__ int   s_si[EB];
    __shared__ int   s_di[EB];
    __shared__ float s_ex[EB];
    int tid = threadIdx.x;
    int ebase = blockIdx.x * EB;
    int nval = EE - ebase; if (nval > EB) nval = EB;
    if (tid < EB && tid < nval) {
        int e = ebase + tid;
        int si = __ldg(src + e), di = __ldg(dst + e);
        float ee = __ldg(el + si) + __ldg(er + di);
        ee = ee > 0.f ? ee : 0.01f * ee;
        float ex = __expf(ee);
        atomicAdd(s + di, ex);
        s_si[tid] = si; s_di[tid] = di; s_ex[tid] = ex;
    }
    __syncthreads();
    int sub  = tid & 15;
    int half = tid >> 4;         // 0..15
    float4 fv[8]; float xv[8]; int dv[8];
    #pragma unroll
    for (int it = 0; it < 8; it++) {
        int le = it*16 + half;
        if (le < nval) {
            int si = s_si[le];
            dv[it] = s_di[le];
            xv[it] = s_ex[le];
            fv[it] = __ldg((const float4*)fsrc + (size_t)si*16 + sub);
        } else dv[it] = -1;
    }
    #pragma unroll
    for (int it = 0; it < 8; it++) {
        if (dv[it] >= 0) {
            float x = xv[it]; float4 f = fv[it];
            red4(z + (size_t)dv[it]*DD + sub*4, x*f.x, x*f.y, x*f.z, x*f.w);
        }
    }
}

// ---------------------------------------------------------------- GAT final
__global__ void gat_final_k(const float* __restrict__ s, float* __restrict__ z) {
    int t = blockIdx.x * blockDim.x + threadIdx.x;
    float sv = s[t >> 6];
    float v = sv > 0.f ? z[t] / sv : 0.f;
    z[t] = v > 0.f ? v : expm1f(v);
}

// -------------------------------------------------- GC scatter (smem-staged)
__global__ void __launch_bounds__(256) gc_scatter_k(
        const int* __restrict__ src, const int* __restrict__ dst,
        const float* __restrict__ fsrc, const float* __restrict__ no,
        float* __restrict__ z) {
    __shared__ int   s_si[EB];
    __shared__ int   s_di[EB];
    __shared__ float s_w[EB];
    int tid = threadIdx.x;
    int ebase = blockIdx.x * EB;
    int nval = EE - ebase; if (nval > EB) nval = EB;
    if (tid < EB && tid < nval) {
        int e = ebase + tid;
        int si = __ldg(src + e), di = __ldg(dst + e);
        s_si[tid] = si; s_di[tid] = di; s_w[tid] = __ldg(no + si);
    }
    __syncthreads();
    int sub  = tid & 15;
    int half = tid >> 4;
    float4 fv[8]; float wv[8]; int dv[8];
    #pragma unroll
    for (int it = 0; it < 8; it++) {
        int le = it*16 + half;
        if (le < nval) {
            int si = s_si[le];
            dv[it] = s_di[le];
            wv[it] = s_w[le];
            fv[it] = __ldg((const float4*)fsrc + (size_t)si*16 + sub);
        } else dv[it] = -1;
    }
    #pragma unroll
    for (int it = 0; it < 8; it++) {
        if (dv[it] >= 0) {
            float c = wv[it]; float4 f = fv[it];
            red4(z + (size_t)dv[it]*DD + sub*4, c*f.x, c*f.y, c*f.z, c*f.w);
        }
    }
}

// ----------------------------------------- GC: ni-scale + 64x64 GEMM + ELU
__global__ void gc_gemm_k(float* __restrict__ z, const float* __restrict__ W,
                          const float* __restrict__ b, const float* __restrict__ ni) {
    __shared__ float Wsh[DD*DD];
    int t = threadIdx.x;
    #pragma unroll
    for (int i = t; i < DD*DD; i += 256) Wsh[i] = W[i];
    __syncthreads();
    int node = blockIdx.x * 8 + (t >> 5);
    int lane = t & 31;
    float* zp = z + (size_t)node*DD;
    float c = ni[node];
    float r0 = zp[lane]*c, r1 = zp[lane+32]*c;
    float a0 = b[lane], a1 = b[lane+32];
    #pragma unroll
    for (int d = 0; d < 32; d++) {
        float v = __shfl_sync(0xffffffffu, r0, d);
        a0 += v*Wsh[d*DD + lane];
        a1 += v*Wsh[d*DD + lane + 32];
    }
    #pragma unroll
    for (int d = 0; d < 32; d++) {
        float v = __shfl_sync(0xffffffffu, r1, d);
        a0 += v*Wsh[(d+32)*DD + lane];
        a1 += v*Wsh[(d+32)*DD + lane + 32];
    }
    zp[lane]      = a0 > 0.f ? a0 : expm1f(a0);
    zp[lane + 32] = a1 > 0.f ? a1 : expm1f(a1);
}

// ---------------------------------------------------- semantic attention score
// 256 thr = 32 node-pairs x 8 h-threads. 64 nodes/block, both planes.
// Thread: 4 rows (2 nodes x 2 planes) x 16 h (pairs 2hq+16j) via FFMA2.
#define NPB 64
#define ZST 68
__global__ void __launch_bounds__(256) sa_score_k(SaP S) {
    extern __shared__ float sm[];
    float* W1sh = sm;                  // 8192
    float* zsh  = sm + DD*HH;          // 2*64*68
    float* b1sh = zsh + 2*NPB*ZST;     // 128
    float* w2sh = b1sh + HH;           // 128
    float* red  = w2sh + HH;           // 2

    int g = blockIdx.y, t = threadIdx.x;
    for (int i = t; i < DD*HH; i += 256) W1sh[i] = S.W1[g][i];
    if (t < HH) { b1sh[t] = S.b1[g][t]; w2sh[t] = S.w2[g][t]; }
    if (t < 2) red[t] = 0.f;

    int nb = blockIdx.x * NPB;
    const float4* base = (const float4*)(g_z + (size_t)(2*g)*ZSZ);
    for (int idx = t; idx < 2*NPB*16; idx += 256) {
        int p = idx >> 10;
        int n = (idx >> 4) & (NPB-1);
        int v = idx & 15;
        float4 val = make_float4(0.f,0.f,0.f,0.f);
        int gn = nb + n;
        if (gn < NN) val = __ldg(base + (size_t)p*(ZSZ/4) + (size_t)gn*16 + v);
        ((float4*)(zsh + (p*NPB + n)*ZST))[v] = val;
    }
    __syncthreads();

    int pair = t >> 3;     // 0..31
    int hq   = t & 7;      // 0..7
    ull acc[4][8];
    #pragma unroll
    for (int j = 0; j < 8; j++) {
        ull b = *(const ull*)(b1sh + 2*hq + 16*j);
        acc[0][j] = b; acc[1][j] = b; acc[2][j] = b; acc[3][j] = b;
    }

    const float* z0 = zsh + (pair*2)*ZST;             // plane0, nodes 2p,2p+1
    const float* z1 = zsh + (NPB + pair*2)*ZST;       // plane1
    for (int d = 0; d < DD; d++) {
        float a0 = z0[d], a1 = z0[ZST + d];
        float c0 = z1[d], c1 = z1[ZST + d];
        ull p0 = pack2(a0, a0), p1 = pack2(a1, a1);
        ull p2 = pack2(c0, c0), p3 = pack2(c1, c1);
        const float* wrow = W1sh + d*HH;
        #pragma unroll
        for (int j = 0; j < 8; j++) {
            ull w = *(const ull*)(wrow + 2*hq + 16*j);
            acc[0][j] = ffma2(p0, w, acc[0][j]);
            acc[1][j] = ffma2(p1, w, acc[1][j]);
            acc[2][j] = ffma2(p2, w, acc[2][j]);
            acc[3][j] = ffma2(p3, w, acc[3][j]);
        }
    }

    float part0 = 0.f, part1 = 0.f;
    #pragma unroll
    for (int r = 0; r < 4; r++) {
        int node = nb + pair*2 + (r & 1);
        if (node >= NN) continue;
        float sv = 0.f;
        #pragma unroll
        for (int j = 0; j < 8; j++) {
            float wa = w2sh[2*hq + 16*j], wb = w2sh[2*hq + 16*j + 1];
            float lo, hi; unpack2(acc[r][j], lo, hi);
            sv += tanha(lo)*wa + tanha(hi)*wb;
        }
        if (r < 2) part0 += sv; else part1 += sv;
    }
    #pragma unroll
    for (int o = 16; o; o >>= 1) {
        part0 += __shfl_down_sync(0xffffffffu, part0, o);
        part1 += __shfl_down_sync(0xffffffffu, part1, o);
    }
    if ((t & 31) == 0) { atomicAdd(&red[0], part0); atomicAdd(&red[1], part1); }
    __syncthreads();
    if (t == 0) {
        atomicAdd(g_wsum + 2*g,     red[0]);
        atomicAdd(g_wsum + 2*g + 1, red[1]);
    }
}

// ---------------------------------------------------------------- beta
__global__ void beta_k() {
    #pragma unroll
    for (int g = 0; g < 4; g++) {
        float w0 = g_wsum[2*g]   * (1.0f/NN);
        float w1 = g_wsum[2*g+1] * (1.0f/NN);
        float m = fmaxf(w0, w1);
        float e0 = __expf(w0-m), e1 = __expf(w1-m);
        float inv = 1.f/(e0+e1);
        g_beta[2*g] = e0*inv; g_beta[2*g+1] = e1*inv;
    }
}

// ---------------------------------------------------------------- combine
__global__ void combine_k(float* __restrict__ out) {
    int t = blockIdx.x * blockDim.x + threadIdx.x;
    const float4* Z = (const float4*)g_z;
    const size_t Pp = ZSZ/4;
    float4 r;
    if (t < NN*16) {
        float b0=g_beta[0], b1=g_beta[1], b4=g_beta[4], b5=g_beta[5];
        float4 x0=Z[t], x1=Z[Pp+t], x4=Z[4*Pp+t], x5=Z[5*Pp+t];
        r.x = b0*x0.x+b1*x1.x+b4*x4.x+b5*x5.x;
        r.y = b0*x0.y+b1*x1.y+b4*x4.y+b5*x5.y;
        r.z = b0*x0.z+b1*x1.z+b4*x4.z+b5*x5.z;
        r.w = b0*x0.w+b1*x1.w+b4*x4.w+b5*x5.w;
    } else {
        size_t u = t - NN*16;
        float b2=g_beta[2], b3=g_beta[3], b6=g_beta[6], b7=g_beta[7];
        float4 x2=Z[2*Pp+u], x3=Z[3*Pp+u], x6=Z[6*Pp+u], x7=Z[7*Pp+u];
        r.x = b2*x2.x+b3*x3.x+b6*x6.x+b7*x7.x;
        r.y = b2*x2.y+b3*x3.y+b6*x6.y+b7*x7.y;
        r.z = b2*x2.z+b3*x3.z+b6*x6.z+b7*x7.z;
        r.w = b2*x2.w+b3*x3.w+b6*x6.w+b7*x7.w;
    }
    ((float4*)out)[t] = r;
}

// ============================================================== host launcher
extern "C" void kernel_launch(void* const* d_in, const int* in_sizes, int n_in,
                              void* d_out, int out_size) {
    const float* feat_user = (const float*)d_in[0];
    const float* feat_item = (const float*)d_in[1];
    const float* attn_l    = (const float*)d_in[2];
    const float* attn_r    = (const float*)d_in[3];
    const float* W_gc      = (const float*)d_in[4];
    const float* b_gc      = (const float*)d_in[5];
    const float* sa_rel_W1 = (const float*)d_in[6];
    const float* sa_rel_b1 = (const float*)d_in[7];
    const float* sa_rel_w2 = (const float*)d_in[8];
    const float* sa_u_W1   = (const float*)d_in[9];
    const float* sa_u_b1   = (const float*)d_in[10];
    const float* sa_u_w2   = (const float*)d_in[11];
    const float* sa_i_W1   = (const float*)d_in[12];
    const float* sa_i_b1   = (const float*)d_in[13];
    const float* sa_i_w2   = (const float*)d_in[14];
    const int* rel_u_src   = (const int*)d_in[15];
    const int* rel_u_dst   = (const int*)d_in[16];
    const int* rel_i_src   = (const int*)d_in[17];
    const int* rel_i_dst   = (const int*)d_in[18];
    const int* mp_u_src    = (const int*)d_in[19];
    const int* mp_u_dst    = (const int*)d_in[20];
    const int* mp_i_src    = (const int*)d_in[21];
    const int* mp_i_dst    = (const int*)d_in[22];
    float* out = (float*)d_out;

    const int* Gs[4] = { rel_u_src, rel_u_src+EE, rel_i_src, rel_i_src+EE };
    const int* Gd[4] = { rel_u_dst, rel_u_dst+EE, rel_i_dst, rel_i_dst+EE };
    const float* Gf[4] = { feat_item, feat_item, feat_user, feat_user };
    const int* Cs[4] = { mp_u_src, mp_u_src+EE, mp_i_src, mp_i_src+EE };
    const int* Cd[4] = { mp_u_dst, mp_u_dst+EE, mp_i_dst, mp_i_dst+EE };
    const float* Cf[4] = { feat_user, feat_user, feat_item, feat_item };

    G4 C; for (int g = 0; g < 4; g++) { C.s[g] = Cs[g]; C.d[g] = Cd[g]; }
    SaP S;
    S.W1[0]=sa_rel_W1; S.b1[0]=sa_rel_b1; S.w2[0]=sa_rel_w2;
    S.W1[1]=sa_rel_W1; S.b1[1]=sa_rel_b1; S.w2[1]=sa_rel_w2;
    S.W1[2]=sa_u_W1;   S.b1[2]=sa_u_b1;   S.w2[2]=sa_u_w2;
    S.W1[3]=sa_i_W1;   S.b1[3]=sa_i_b1;   S.w2[3]=sa_i_w2;

    // Resolve device-symbol base addresses (host query; no allocation).
    float* z_base;  float* s_base;  float* el_base;
    float* er_base; float* no_base; float* ni_base;
    cudaGetSymbolAddress((void**)&z_base,  g_z);
    cudaGetSymbolAddress((void**)&s_base,  g_s);
    cudaGetSymbolAddress((void**)&el_base, g_el);
    cudaGetSymbolAddress((void**)&er_base, g_er);
    cudaGetSymbolAddress((void**)&no_base, g_no);
    cudaGetSymbolAddress((void**)&ni_base, g_ni);

    const int TB = 256;
    const int SCAT_BLKS = (EE + EB - 1) / EB;   // 3907
    const int ZP_BLKS   = ZSZ / 4 / TB;         // 3125

    zero_nodes_k<<<(4*NN + TB - 1)/TB, TB>>>();
    ler_all_k<<<dim3(NN*32/TB, 2), TB>>>(feat_user, feat_item, attn_l, attn_r);
    deg_k<<<dim3((EE + TB - 1)/TB, 4), TB>>>(C);
    norm_k<<<(4*NN + TB - 1)/TB, TB>>>();

    // GAT graphs: sequential per-graph for L2 residency
    for (int g = 0; g < 4; g++) {
        float* z = z_base + (size_t)g * ZSZ;
        zero_plane_k<<<ZP_BLKS, TB>>>(z);
        gat_scatter_k<<<SCAT_BLKS, TB>>>(Gs[g], Gd[g], Gf[g],
                                         el_base + g*NN, er_base + g*NN,
                                         s_base + g*NN, z);
        gat_final_k<<<ZSZ/TB, TB>>>(s_base + g*NN, z);
    }
    // GC graphs: same sequencing
    for (int g = 0; g < 4; g++) {
        float* z = z_base + (size_t)(4+g) * ZSZ;
        zero_plane_k<<<ZP_BLKS, TB>>>(z);
        gc_scatter_k<<<SCAT_BLKS, TB>>>(Cs[g], Cd[g], Cf[g], no_base + g*NN, z);
        gc_gemm_k<<<NN/8, TB>>>(z, W_gc + g*DD*DD, b_gc + g*DD, ni_base + g*NN);
    }

    int sa_smem = (DD*HH + 2*NPB*ZST + HH + HH + 2) * sizeof(float);
    cudaFuncSetAttribute(sa_score_k, cudaFuncAttributeMaxDynamicSharedMemorySize, sa_smem);
    sa_score_k<<<dim3((NN + NPB - 1)/NPB, 4), TB, sa_smem>>>(S);

    beta_k<<<1, 1>>>();
    combine_k<<<2*NN*16/TB, TB>>>(out);
}

// round 6
// speedup vs baseline: 2.0588x; 1.0513x over previous
#include <cuda_runtime.h>

#define NN 50000
#define DD 64
#define HH 128
#define EE 500000
#define ZSZ (NN*DD)
#define EB 128          // edges per scatter block

typedef unsigned long long ull;

// ---------------------------------------------------------------- scratch
__device__ float g_z[(size_t)8*ZSZ];   // 0-3 GAT planes, 4-7 GC planes
__device__ float g_s[4*NN];            // GAT softmax denominators
__device__ float g_el[4*NN];
__device__ float g_er[4*NN];
__device__ float g_no[4*NN];           // GC out-deg counts
__device__ float g_ni[4*NN];           // GC in-deg counts
__device__ float g_wsum[8];

struct G4 { const int* s[4]; const int* d[4]; };
struct SaP { const float* W1[4]; const float* b1[4]; const float* w2[4]; };

// ---------------------------------------------------------------- utils
__device__ __forceinline__ ull pack2(float a, float b) {
    ull r; asm("mov.b64 %0, {%1,%2};" : "=l"(r) : "f"(a), "f"(b)); return r;
}
__device__ __forceinline__ void unpack2(ull v, float& a, float& b) {
    asm("mov.b64 {%0,%1}, %2;" : "=f"(a), "=f"(b) : "l"(v));
}
__device__ __forceinline__ ull ffma2(ull a, ull b, ull c) {
    ull d; asm("fma.rn.f32x2 %0, %1, %2, %3;" : "=l"(d) : "l"(a), "l"(b), "l"(c));
    return d;
}
__device__ __forceinline__ float tanha(float x) {
    float r; asm("tanh.approx.f32 %0, %1;" : "=f"(r) : "f"(x)); return r;
}
__device__ __forceinline__ void red4(float* p, float a, float b, float c, float d) {
    asm volatile("red.global.add.v4.f32 [%0], {%1, %2, %3, %4};"
                 :: "l"(p), "f"(a), "f"(b), "f"(c), "f"(d));   // no mem clobber: keep MLP
}

// ------------------------------------- zero: planes 0,1 + all node arrays
__global__ void zero_all_k(float* __restrict__ z01) {
    int t = blockIdx.x * blockDim.x + threadIdx.x;      // grid covers 2*ZSZ/4
    ((float4*)z01)[t] = make_float4(0.f,0.f,0.f,0.f);
    if (t < 4*NN) { g_s[t] = 0.f; g_no[t] = 0.f; g_ni[t] = 0.f; }
    if (t < 8) g_wsum[t] = 0.f;
}

// -------------------------------------- fused el/er for all 4 GAT relations
__global__ void ler_all_k(const float* __restrict__ feat_user,
                          const float* __restrict__ feat_item,
                          const float* __restrict__ attn_l,
                          const float* __restrict__ attn_r) {
    int tbl = blockIdx.y;
    int w = (blockIdx.x * blockDim.x + threadIdx.x) >> 5;
    int lane = threadIdx.x & 31;
    const float* f = (tbl == 0 ? feat_user : feat_item) + (size_t)w * DD;
    float f0 = f[lane], f1 = f[lane + 32];
    const float* v0; const float* v1; const float* v2; const float* v3;
    if (tbl == 0) { v0 = attn_r; v1 = attn_r + DD; v2 = attn_l + 2*DD; v3 = attn_l + 3*DD; }
    else          { v0 = attn_l; v1 = attn_l + DD; v2 = attn_r + 2*DD; v3 = attn_r + 3*DD; }
    float s0 = f0*__ldg(v0+lane) + f1*__ldg(v0+lane+32);
    float s1 = f0*__ldg(v1+lane) + f1*__ldg(v1+lane+32);
    float s2 = f0*__ldg(v2+lane) + f1*__ldg(v2+lane+32);
    float s3 = f0*__ldg(v3+lane) + f1*__ldg(v3+lane+32);
    #pragma unroll
    for (int o = 16; o; o >>= 1) {
        s0 += __shfl_down_sync(0xffffffffu, s0, o);
        s1 += __shfl_down_sync(0xffffffffu, s1, o);
        s2 += __shfl_down_sync(0xffffffffu, s2, o);
        s3 += __shfl_down_sync(0xffffffffu, s3, o);
    }
    if (lane == 0) {
        if (tbl == 0) { g_er[w] = s0; g_er[NN+w] = s1; g_el[2*NN+w] = s2; g_el[3*NN+w] = s3; }
        else          { g_el[w] = s0; g_el[NN+w] = s1; g_er[2*NN+w] = s2; g_er[3*NN+w] = s3; }
    }
}

// ---------------------------------------------------------------- GC degrees
__global__ void deg_k(G4 C) {
    int g = blockIdx.y;
    int e = blockIdx.x * blockDim.x + threadIdx.x;
    if (e >= EE) return;
    atomicAdd(g_no + g*NN + __ldg(C.s[g] + e), 1.f);
    atomicAdd(g_ni + g*NN + __ldg(C.d[g] + e), 1.f);
}

// --------------------------------- GAT scatter (smem-staged, pair via y)
__global__ void __launch_bounds__(256) gat_scatter_k(
        const int* __restrict__ src, const int* __restrict__ dst,
        const float* __restrict__ fsrc,
        const float* __restrict__ el, const float* __restrict__ er,
        float* __restrict__ s, float* __restrict__ z) {
    int g = blockIdx.y;
    src += (size_t)g*EE;  dst += (size_t)g*EE;
    el  += (size_t)g*NN;  er  += (size_t)g*NN;  s += (size_t)g*NN;
    z   += (size_t)g*ZSZ;
    __shared__ int   s_si[EB];
    __shared__ int   s_di[EB];
    __shared__ float s_ex[EB];
    int tid = threadIdx.x;
    int ebase = blockIdx.x * EB;
    int nval = EE - ebase; if (nval > EB) nval = EB;
    if (tid < EB && tid < nval) {
        int e = ebase + tid;
        int si = __ldg(src + e), di = __ldg(dst + e);
        float ee = __ldg(el + si) + __ldg(er + di);
        ee = ee > 0.f ? ee : 0.01f * ee;
        float ex = __expf(ee);
        atomicAdd(s + di, ex);
        s_si[tid] = si; s_di[tid] = di; s_ex[tid] = ex;
    }
    __syncthreads();
    int sub  = tid & 15;
    int half = tid >> 4;
    float4 fv[8]; float xv[8]; int dv[8];
    #pragma unroll
    for (int it = 0; it < 8; it++) {
        int le = it*16 + half;
        if (le < nval) {
            int si = s_si[le];
            dv[it] = s_di[le];
            xv[it] = s_ex[le];
            fv[it] = __ldg((const float4*)fsrc + (size_t)si*16 + sub);
        } else dv[it] = -1;
    }
    #pragma unroll
    for (int it = 0; it < 8; it++) {
        if (dv[it] >= 0) {
            float x = xv[it]; float4 f = fv[it];
            red4(z + (size_t)dv[it]*DD + sub*4, x*f.x, x*f.y, x*f.z, x*f.w);
        }
    }
}

// ----------------------- GAT finalize (pair) + zero next pair's planes
__global__ void gat_final_zero_k(const float* __restrict__ s, float* __restrict__ z,
                                 float* __restrict__ zn) {
    int g = blockIdx.y;
    s += (size_t)g*NN;  z += (size_t)g*ZSZ;
    int t = blockIdx.x * blockDim.x + threadIdx.x;      // grid.x covers ZSZ
    float sv = s[t >> 6];
    float v = sv > 0.f ? z[t] / sv : 0.f;
    z[t] = v > 0.f ? v : expm1f(v);
    if (zn && t < ZSZ/4)
        ((float4*)(zn + (size_t)g*ZSZ))[t] = make_float4(0.f,0.f,0.f,0.f);
}

// ----------------------------- GC scatter (smem-staged, pair via y)
__global__ void __launch_bounds__(256) gc_scatter_k(
        const int* __restrict__ src, const int* __restrict__ dst,
        const float* __restrict__ fsrc, const float* __restrict__ no,
        float* __restrict__ z) {
    int g = blockIdx.y;
    src += (size_t)g*EE;  dst += (size_t)g*EE;
    no  += (size_t)g*NN;  z   += (size_t)g*ZSZ;
    __shared__ int   s_si[EB];
    __shared__ int   s_di[EB];
    __shared__ float s_w[EB];
    int tid = threadIdx.x;
    int ebase = blockIdx.x * EB;
    int nval = EE - ebase; if (nval > EB) nval = EB;
    if (tid < EB && tid < nval) {
        int e = ebase + tid;
        int si = __ldg(src + e), di = __ldg(dst + e);
        float cnt = __ldg(no + si);
        s_si[tid] = si; s_di[tid] = di;
        s_w[tid] = rsqrtf(fmaxf(cnt, 1.f));
    }
    __syncthreads();
    int sub  = tid & 15;
    int half = tid >> 4;
    float4 fv[8]; float wv[8]; int dv[8];
    #pragma unroll
    for (int it = 0; it < 8; it++) {
        int le = it*16 + half;
        if (le < nval) {
            int si = s_si[le];
            dv[it] = s_di[le];
            wv[it] = s_w[le];
            fv[it] = __ldg((const float4*)fsrc + (size_t)si*16 + sub);
        } else dv[it] = -1;
    }
    #pragma unroll
    for (int it = 0; it < 8; it++) {
        if (dv[it] >= 0) {
            float c = wv[it]; float4 f = fv[it];
            red4(z + (size_t)dv[it]*DD + sub*4, c*f.x, c*f.y, c*f.z, c*f.w);
        }
    }
}

// -------------- GC: ni-scale + 64x64 GEMM + ELU (pair) + optional zero next
__global__ void gc_gemm_zero_k(float* __restrict__ z, const float* __restrict__ W_gc,
                               const float* __restrict__ b_gc,
                               const float* __restrict__ ni, float* __restrict__ zn) {
    __shared__ float Wsh[DD*DD];
    int g = blockIdx.y, t = threadIdx.x;
    const float* W = W_gc + g*DD*DD;
    const float* b = b_gc + g*DD;
    z  += (size_t)g*ZSZ;  ni += (size_t)g*NN;
    #pragma unroll
    for (int i = t; i < DD*DD; i += 256) Wsh[i] = W[i];
    __syncthreads();
    int node = blockIdx.x * 8 + (t >> 5);
    int lane = t & 31;
    float* zp = z + (size_t)node*DD;
    float c = rsqrtf(fmaxf(ni[node], 1.f));
    float r0 = zp[lane]*c, r1 = zp[lane+32]*c;
    float a0 = b[lane], a1 = b[lane+32];
    #pragma unroll
    for (int d = 0; d < 32; d++) {
        float v = __shfl_sync(0xffffffffu, r0, d);
        a0 += v*Wsh[d*DD + lane];
        a1 += v*Wsh[d*DD + lane + 32];
    }
    #pragma unroll
    for (int d = 0; d < 32; d++) {
        float v = __shfl_sync(0xffffffffu, r1, d);
        a0 += v*Wsh[(d+32)*DD + lane];
        a1 += v*Wsh[(d+32)*DD + lane + 32];
    }
    zp[lane]      = a0 > 0.f ? a0 : expm1f(a0);
    zp[lane + 32] = a1 > 0.f ? a1 : expm1f(a1);
    if (zn) {
        int idx = blockIdx.x * 256 + t;                 // 6250*256 = 1.6M >= ZSZ/4
        if (idx < ZSZ/4)
            ((float4*)(zn + (size_t)g*ZSZ))[idx] = make_float4(0.f,0.f,0.f,0.f);
    }
}

// ---------------------------------------------------- semantic attention score
#define NPB 64
#define ZST 68
__global__ void __launch_bounds__(256) sa_score_k(SaP S) {
    extern __shared__ float sm[];
    float* W1sh = sm;                  // 8192
    float* zsh  = sm + DD*HH;          // 2*64*68
    float* b1sh = zsh + 2*NPB*ZST;     // 128
    float* w2sh = b1sh + HH;           // 128
    float* red  = w2sh + HH;           // 2

    int g = blockIdx.y, t = threadIdx.x;
    for (int i = t; i < DD*HH; i += 256) W1sh[i] = S.W1[g][i];
    if (t < HH) { b1sh[t] = S.b1[g][t]; w2sh[t] = S.w2[g][t]; }
    if (t < 2) red[t] = 0.f;

    int nb = blockIdx.x * NPB;
    const float4* base = (const float4*)(g_z + (size_t)(2*g)*ZSZ);
    for (int idx = t; idx < 2*NPB*16; idx += 256) {
        int p = idx >> 10;
        int n = (idx >> 4) & (NPB-1);
        int v = idx & 15;
        float4 val = make_float4(0.f,0.f,0.f,0.f);
        int gn = nb + n;
        if (gn < NN) val = __ldg(base + (size_t)p*(ZSZ/4) + (size_t)gn*16 + v);
        ((float4*)(zsh + (p*NPB + n)*ZST))[v] = val;
    }
    __syncthreads();

    int pair = t >> 3;
    int hq   = t & 7;
    ull acc[4][8];
    #pragma unroll
    for (int j = 0; j < 8; j++) {
        ull b = *(const ull*)(b1sh + 2*hq + 16*j);
        acc[0][j] = b; acc[1][j] = b; acc[2][j] = b; acc[3][j] = b;
    }

    const float* z0 = zsh + (pair*2)*ZST;
    const float* z1 = zsh + (NPB + pair*2)*ZST;
    for (int d = 0; d < DD; d++) {
        float a0 = z0[d], a1 = z0[ZST + d];
        float c0 = z1[d], c1 = z1[ZST + d];
        ull p0 = pack2(a0, a0), p1 = pack2(a1, a1);
        ull p2 = pack2(c0, c0), p3 = pack2(c1, c1);
        const float* wrow = W1sh + d*HH;
        #pragma unroll
        for (int j = 0; j < 8; j++) {
            ull w = *(const ull*)(wrow + 2*hq + 16*j);
            acc[0][j] = ffma2(p0, w, acc[0][j]);
            acc[1][j] = ffma2(p1, w, acc[1][j]);
            acc[2][j] = ffma2(p2, w, acc[2][j]);
            acc[3][j] = ffma2(p3, w, acc[3][j]);
        }
    }

    float part0 = 0.f, part1 = 0.f;
    #pragma unroll
    for (int r = 0; r < 4; r++) {
        int node = nb + pair*2 + (r & 1);
        if (node >= NN) continue;
        float sv = 0.f;
        #pragma unroll
        for (int j = 0; j < 8; j++) {
            float wa = w2sh[2*hq + 16*j], wb = w2sh[2*hq + 16*j + 1];
            float lo, hi; unpack2(acc[r][j], lo, hi);
            sv += tanha(lo)*wa + tanha(hi)*wb;
        }
        if (r < 2) part0 += sv; else part1 += sv;
    }
    #pragma unroll
    for (int o = 16; o; o >>= 1) {
        part0 += __shfl_down_sync(0xffffffffu, part0, o);
        part1 += __shfl_down_sync(0xffffffffu, part1, o);
    }
    if ((t & 31) == 0) { atomicAdd(&red[0], part0); atomicAdd(&red[1], part1); }
    __syncthreads();
    if (t == 0) {
        atomicAdd(g_wsum + 2*g,     red[0]);
        atomicAdd(g_wsum + 2*g + 1, red[1]);
    }
}

// ---------------------------------------------- combine (beta computed inline)
__global__ void combine_k(float* __restrict__ out) {
    __shared__ float bsh[8];
    int tt = threadIdx.x;
    if (tt == 0) {
        #pragma unroll
        for (int g = 0; g < 4; g++) {
            float w0 = g_wsum[2*g]   * (1.0f/NN);
            float w1 = g_wsum[2*g+1] * (1.0f/NN);
            float m = fmaxf(w0, w1);
            float e0 = __expf(w0-m), e1 = __expf(w1-m);
            float inv = 1.f/(e0+e1);
            bsh[2*g] = e0*inv; bsh[2*g+1] = e1*inv;
        }
    }
    __syncthreads();
    int t = blockIdx.x * blockDim.x + tt;
    const float4* Z = (const float4*)g_z;
    const size_t Pp = ZSZ/4;
    float4 r;
    if (t < NN*16) {
        float b0=bsh[0], b1=bsh[1], b4=bsh[4], b5=bsh[5];
        float4 x0=Z[t], x1=Z[Pp+t], x4=Z[4*Pp+t], x5=Z[5*Pp+t];
        r.x = b0*x0.x+b1*x1.x+b4*x4.x+b5*x5.x;
        r.y = b0*x0.y+b1*x1.y+b4*x4.y+b5*x5.y;
        r.z = b0*x0.z+b1*x1.z+b4*x4.z+b5*x5.z;
        r.w = b0*x0.w+b1*x1.w+b4*x4.w+b5*x5.w;
    } else {
        size_t u = t - NN*16;
        float b2=bsh[2], b3=bsh[3], b6=bsh[6], b7=bsh[7];
        float4 x2=Z[2*Pp+u], x3=Z[3*Pp+u], x6=Z[6*Pp+u], x7=Z[7*Pp+u];
        r.x = b2*x2.x+b3*x3.x+b6*x6.x+b7*x7.x;
        r.y = b2*x2.y+b3*x3.y+b6*x6.y+b7*x7.y;
        r.z = b2*x2.z+b3*x3.z+b6*x6.z+b7*x7.z;
        r.w = b2*x2.w+b3*x3.w+b6*x6.w+b7*x7.w;
    }
    ((float4*)out)[t] = r;
}

// ============================================================== host launcher
extern "C" void kernel_launch(void* const* d_in, const int* in_sizes, int n_in,
                              void* d_out, int out_size) {
    const float* feat_user = (const float*)d_in[0];
    const float* feat_item = (const float*)d_in[1];
    const float* attn_l    = (const float*)d_in[2];
    const float* attn_r    = (const float*)d_in[3];
    const float* W_gc      = (const float*)d_in[4];
    const float* b_gc      = (const float*)d_in[5];
    const float* sa_rel_W1 = (const float*)d_in[6];
    const float* sa_rel_b1 = (const float*)d_in[7];
    const float* sa_rel_w2 = (const float*)d_in[8];
    const float* sa_u_W1   = (const float*)d_in[9];
    const float* sa_u_b1   = (const float*)d_in[10];
    const float* sa_u_w2   = (const float*)d_in[11];
    const float* sa_i_W1   = (const float*)d_in[12];
    const float* sa_i_b1   = (const float*)d_in[13];
    const float* sa_i_w2   = (const float*)d_in[14];
    const int* rel_u_src   = (const int*)d_in[15];
    const int* rel_u_dst   = (const int*)d_in[16];
    const int* rel_i_src   = (const int*)d_in[17];
    const int* rel_i_dst   = (const int*)d_in[18];
    const int* mp_u_src    = (const int*)d_in[19];
    const int* mp_u_dst    = (const int*)d_in[20];
    const int* mp_i_src    = (const int*)d_in[21];
    const int* mp_i_dst    = (const int*)d_in[22];
    float* out = (float*)d_out;

    G4 C;
    C.s[0]=mp_u_src;    C.d[0]=mp_u_dst;
    C.s[1]=mp_u_src+EE; C.d[1]=mp_u_dst+EE;
    C.s[2]=mp_i_src;    C.d[2]=mp_i_dst;
    C.s[3]=mp_i_src+EE; C.d[3]=mp_i_dst+EE;
    SaP S;
    S.W1[0]=sa_rel_W1; S.b1[0]=sa_rel_b1; S.w2[0]=sa_rel_w2;
    S.W1[1]=sa_rel_W1; S.b1[1]=sa_rel_b1; S.w2[1]=sa_rel_w2;
    S.W1[2]=sa_u_W1;   S.b1[2]=sa_u_b1;   S.w2[2]=sa_u_w2;
    S.W1[3]=sa_i_W1;   S.b1[3]=sa_i_b1;   S.w2[3]=sa_i_w2;

    float* z_base;  float* s_base;  float* el_base;
    float* er_base; float* no_base; float* ni_base;
    cudaGetSymbolAddress((void**)&z_base,  g_z);
    cudaGetSymbolAddress((void**)&s_base,  g_s);
    cudaGetSymbolAddress((void**)&el_base, g_el);
    cudaGetSymbolAddress((void**)&er_base, g_er);
    cudaGetSymbolAddress((void**)&no_base, g_no);
    cudaGetSymbolAddress((void**)&ni_base, g_ni);

    const int TB = 256;
    const int SCAT_BLKS = (EE + EB - 1) / EB;   // 3907
    const int ZF_BLKS   = ZSZ / TB;             // 12500

    // planes 0,1 + node arrays
    zero_all_k<<<2*ZSZ/4/TB, TB>>>(z_base);
    ler_all_k<<<dim3(NN*32/TB, 2), TB>>>(feat_user, feat_item, attn_l, attn_r);
    deg_k<<<dim3((EE + TB - 1)/TB, 4), TB>>>(C);

    // GAT pair 0: graphs 0,1 (rel_u, feat_item) -> planes 0,1 ; zero 2,3
    gat_scatter_k<<<dim3(SCAT_BLKS, 2), TB>>>(rel_u_src, rel_u_dst, feat_item,
                                              el_base, er_base, s_base, z_base);
    gat_final_zero_k<<<dim3(ZF_BLKS, 2), TB>>>(s_base, z_base, z_base + (size_t)2*ZSZ);
    // GAT pair 1: graphs 2,3 (rel_i, feat_user) -> planes 2,3 ; zero 4,5
    gat_scatter_k<<<dim3(SCAT_BLKS, 2), TB>>>(rel_i_src, rel_i_dst, feat_user,
                                              el_base + 2*NN, er_base + 2*NN,
                                              s_base + 2*NN, z_base + (size_t)2*ZSZ);
    gat_final_zero_k<<<dim3(ZF_BLKS, 2), TB>>>(s_base + 2*NN, z_base + (size_t)2*ZSZ,
                                               z_base + (size_t)4*ZSZ);

    // GC pair 0: graphs 0,1 (mp_u, feat_user) -> planes 4,5 ; zero 6,7
    gc_scatter_k<<<dim3(SCAT_BLKS, 2), TB>>>(mp_u_src, mp_u_dst, feat_user,
                                             no_base, z_base + (size_t)4*ZSZ);
    gc_gemm_zero_k<<<dim3(NN/8, 2), TB>>>(z_base + (size_t)4*ZSZ, W_gc, b_gc,
                                          ni_base, z_base + (size_t)6*ZSZ);
    // GC pair 1: graphs 2,3 (mp_i, feat_item) -> planes 6,7
    gc_scatter_k<<<dim3(SCAT_BLKS, 2), TB>>>(mp_i_src, mp_i_dst, feat_item,
                                             no_base + 2*NN, z_base + (size_t)6*ZSZ);
    gc_gemm_zero_k<<<dim3(NN/8, 2), TB>>>(z_base + (size_t)6*ZSZ, W_gc + 2*DD*DD,
                                          b_gc + 2*DD, ni_base + 2*NN, nullptr);

    int sa_smem = (DD*HH + 2*NPB*ZST + HH + HH + 2) * sizeof(float);
    cudaFuncSetAttribute(sa_score_k, cudaFuncAttributeMaxDynamicSharedMemorySize, sa_smem);
    sa_score_k<<<dim3((NN + NPB - 1)/NPB, 4), TB, sa_smem>>>(S);

    combine_k<<<2*NN*16/TB, TB>>>(out);
}

// round 7
// speedup vs baseline: 2.1079x; 1.0239x over previous
#include <cuda_runtime.h>

#define NN 50000
#define DD 64
#define HH 128
#define EE 500000
#define ZSZ (NN*DD)
#define EB 128          // edges per scatter block

typedef unsigned long long ull;

// ---------------------------------------------------------------- scratch
__device__ float g_z[(size_t)8*ZSZ];   // 0-3 GAT planes, 4-7 GC planes
__device__ float g_s[4*NN];            // GAT softmax denominators
__device__ float g_el[4*NN];
__device__ float g_er[4*NN];
__device__ float g_no[4*NN];           // GC out-deg counts
__device__ float g_ni[4*NN];           // GC in-deg counts
__device__ float g_wsum[8];

struct G4 { const int* s[4]; const int* d[4]; };
struct SaP { const float* W1[4]; const float* b1[4]; const float* w2[4]; };

// ---------------------------------------------------------------- utils
__device__ __forceinline__ ull pack2(float a, float b) {
    ull r; asm("mov.b64 %0, {%1,%2};" : "=l"(r) : "f"(a), "f"(b)); return r;
}
__device__ __forceinline__ void unpack2(ull v, float& a, float& b) {
    asm("mov.b64 {%0,%1}, %2;" : "=f"(a), "=f"(b) : "l"(v));
}
__device__ __forceinline__ ull ffma2(ull a, ull b, ull c) {
    ull d; asm("fma.rn.f32x2 %0, %1, %2, %3;" : "=l"(d) : "l"(a), "l"(b), "l"(c));
    return d;
}
__device__ __forceinline__ float tanha(float x) {
    float r; asm("tanh.approx.f32 %0, %1;" : "=f"(r) : "f"(x)); return r;
}
__device__ __forceinline__ float elu(float x) { return x > 0.f ? x : expm1f(x); }
__device__ __forceinline__ void red4(float* p, float a, float b, float c, float d) {
    asm volatile("red.global.add.v4.f32 [%0], {%1, %2, %3, %4};"
                 :: "l"(p), "f"(a), "f"(b), "f"(c), "f"(d));   // no mem clobber: keep MLP
}

// ---------------- fused prologue: y=0 zero planes0/1+nodes; y=1/2 ler; y=3 deg
__global__ void pre_k(float* __restrict__ z01,
                      const float* __restrict__ feat_user,
                      const float* __restrict__ feat_item,
                      const float* __restrict__ attn_l,
                      const float* __restrict__ attn_r,
                      G4 C) {
    int y = blockIdx.y;
    int gid = blockIdx.x * blockDim.x + threadIdx.x;      // grid.x*256 = 1.6M
    if (y == 0) {
        ((float4*)z01)[gid] = make_float4(0.f,0.f,0.f,0.f);   // 2 planes = 1.6M float4
        if (gid < 4*NN) { g_s[gid] = 0.f; g_no[gid] = 0.f; g_ni[gid] = 0.f; }
        if (gid < 8) g_wsum[gid] = 0.f;
        return;
    }
    if (y == 3) {
        #pragma unroll
        for (int k = 0; k < 2; k++) {
            int i = gid + k * 1600000;
            if (i < 4*EE) {
                int g = i / EE, e = i - g*EE;
                atomicAdd(g_no + g*NN + __ldg(C.s[g] + e), 1.f);
                atomicAdd(g_ni + g*NN + __ldg(C.d[g] + e), 1.f);
            }
        }
        return;
    }
    // y=1: user table ; y=2: item table
    int tbl = y - 1;
    int w = gid >> 5;
    int lane = threadIdx.x & 31;
    const float* f = (tbl == 0 ? feat_user : feat_item) + (size_t)w * DD;
    float f0 = f[lane], f1 = f[lane + 32];
    const float* v0; const float* v1; const float* v2; const float* v3;
    if (tbl == 0) { v0 = attn_r; v1 = attn_r + DD; v2 = attn_l + 2*DD; v3 = attn_l + 3*DD; }
    else          { v0 = attn_l; v1 = attn_l + DD; v2 = attn_r + 2*DD; v3 = attn_r + 3*DD; }
    float s0 = f0*__ldg(v0+lane) + f1*__ldg(v0+lane+32);
    float s1 = f0*__ldg(v1+lane) + f1*__ldg(v1+lane+32);
    float s2 = f0*__ldg(v2+lane) + f1*__ldg(v2+lane+32);
    float s3 = f0*__ldg(v3+lane) + f1*__ldg(v3+lane+32);
    #pragma unroll
    for (int o = 16; o; o >>= 1) {
        s0 += __shfl_down_sync(0xffffffffu, s0, o);
        s1 += __shfl_down_sync(0xffffffffu, s1, o);
        s2 += __shfl_down_sync(0xffffffffu, s2, o);
        s3 += __shfl_down_sync(0xffffffffu, s3, o);
    }
    if (lane == 0) {
        if (tbl == 0) { g_er[w] = s0; g_er[NN+w] = s1; g_el[2*NN+w] = s2; g_el[3*NN+w] = s3; }
        else          { g_el[w] = s0; g_el[NN+w] = s1; g_er[2*NN+w] = s2; g_er[3*NN+w] = s3; }
    }
}

// --------------------------------- GAT scatter (smem-staged, pair via y)
__global__ void __launch_bounds__(256, 5) gat_scatter_k(
        const int* __restrict__ src, const int* __restrict__ dst,
        const float* __restrict__ fsrc,
        const float* __restrict__ el, const float* __restrict__ er,
        float* __restrict__ s, float* __restrict__ z) {
    int g = blockIdx.y;
    src += (size_t)g*EE;  dst += (size_t)g*EE;
    el  += (size_t)g*NN;  er  += (size_t)g*NN;  s += (size_t)g*NN;
    z   += (size_t)g*ZSZ;
    __shared__ int   s_si[EB];
    __shared__ int   s_di[EB];
    __shared__ float s_ex[EB];
    int tid = threadIdx.x;
    int ebase = blockIdx.x * EB;
    int nval = EE - ebase; if (nval > EB) nval = EB;
    if (tid < EB && tid < nval) {
        int e = ebase + tid;
        int si = __ldg(src + e), di = __ldg(dst + e);
        float ee = __ldg(el + si) + __ldg(er + di);
        ee = ee > 0.f ? ee : 0.01f * ee;
        float ex = __expf(ee);
        atomicAdd(s + di, ex);
        s_si[tid] = si; s_di[tid] = di; s_ex[tid] = ex;
    }
    __syncthreads();
    int sub  = tid & 15;
    int half = tid >> 4;
    float4 fv[8];                       // only the feature rows live in regs
    #pragma unroll
    for (int it = 0; it < 8; it++) {
        int le = it*16 + half;
        if (le < nval)
            fv[it] = __ldg((const float4*)fsrc + (size_t)s_si[le]*16 + sub);
    }
    #pragma unroll
    for (int it = 0; it < 8; it++) {
        int le = it*16 + half;
        if (le < nval) {
            float x = s_ex[le]; int d = s_di[le]; float4 f = fv[it];
            red4(z + (size_t)d*DD + sub*4, x*f.x, x*f.y, x*f.z, x*f.w);
        }
    }
}

// -------------- GAT finalize (pair, float4) + zero next pair's planes
__global__ void gat_final_zero_k(const float* __restrict__ s, float* __restrict__ z,
                                 float* __restrict__ zn) {
    int g = blockIdx.y;
    s += (size_t)g*NN;  z += (size_t)g*ZSZ;
    int t = blockIdx.x * blockDim.x + threadIdx.x;      // grid.x covers ZSZ/4
    float sv = s[t >> 4];
    float inv = sv > 0.f ? __frcp_rn(sv) : 0.f;
    float4 v = ((float4*)z)[t];
    v.x = elu(v.x * inv); v.y = elu(v.y * inv);
    v.z = elu(v.z * inv); v.w = elu(v.w * inv);
    ((float4*)z)[t] = v;
    if (zn)
        ((float4*)(zn + (size_t)g*ZSZ))[t] = make_float4(0.f,0.f,0.f,0.f);
}

// ----------------------------- GC scatter (smem-staged, pair via y)
__global__ void __launch_bounds__(256, 5) gc_scatter_k(
        const int* __restrict__ src, const int* __restrict__ dst,
        const float* __restrict__ fsrc, const float* __restrict__ no,
        float* __restrict__ z) {
    int g = blockIdx.y;
    src += (size_t)g*EE;  dst += (size_t)g*EE;
    no  += (size_t)g*NN;  z   += (size_t)g*ZSZ;
    __shared__ int   s_si[EB];
    __shared__ int   s_di[EB];
    __shared__ float s_w[EB];
    int tid = threadIdx.x;
    int ebase = blockIdx.x * EB;
    int nval = EE - ebase; if (nval > EB) nval = EB;
    if (tid < EB && tid < nval) {
        int e = ebase + tid;
        int si = __ldg(src + e), di = __ldg(dst + e);
        float cnt = __ldg(no + si);
        s_si[tid] = si; s_di[tid] = di;
        s_w[tid] = rsqrtf(fmaxf(cnt, 1.f));
    }
    __syncthreads();
    int sub  = tid & 15;
    int half = tid >> 4;
    float4 fv[8];
    #pragma unroll
    for (int it = 0; it < 8; it++) {
        int le = it*16 + half;
        if (le < nval)
            fv[it] = __ldg((const float4*)fsrc + (size_t)s_si[le]*16 + sub);
    }
    #pragma unroll
    for (int it = 0; it < 8; it++) {
        int le = it*16 + half;
        if (le < nval) {
            float c = s_w[le]; int d = s_di[le]; float4 f = fv[it];
            red4(z + (size_t)d*DD + sub*4, c*f.x, c*f.y, c*f.z, c*f.w);
        }
    }
}

// -------------- GC: ni-scale + 64x64 GEMM + ELU (pair) + optional zero next
__global__ void gc_gemm_zero_k(float* __restrict__ z, const float* __restrict__ W_gc,
                               const float* __restrict__ b_gc,
                               const float* __restrict__ ni, float* __restrict__ zn) {
    __shared__ float Wsh[DD*DD];
    int g = blockIdx.y, t = threadIdx.x;
    const float* W = W_gc + g*DD*DD;
    const float* b = b_gc + g*DD;
    z  += (size_t)g*ZSZ;  ni += (size_t)g*NN;
    #pragma unroll
    for (int i = t; i < DD*DD; i += 256) Wsh[i] = W[i];
    __syncthreads();
    int node = blockIdx.x * 8 + (t >> 5);
    int lane = t & 31;
    float* zp = z + (size_t)node*DD;
    float c = rsqrtf(fmaxf(ni[node], 1.f));
    float r0 = zp[lane]*c, r1 = zp[lane+32]*c;
    float a0 = b[lane], a1 = b[lane+32];
    #pragma unroll
    for (int d = 0; d < 32; d++) {
        float v = __shfl_sync(0xffffffffu, r0, d);
        a0 += v*Wsh[d*DD + lane];
        a1 += v*Wsh[d*DD + lane + 32];
    }
    #pragma unroll
    for (int d = 0; d < 32; d++) {
        float v = __shfl_sync(0xffffffffu, r1, d);
        a0 += v*Wsh[(d+32)*DD + lane];
        a1 += v*Wsh[(d+32)*DD + lane + 32];
    }
    zp[lane]      = a0 > 0.f ? a0 : expm1f(a0);
    zp[lane + 32] = a1 > 0.f ? a1 : expm1f(a1);
    if (zn) {
        int idx = blockIdx.x * 256 + t;                 // 6250*256 = 1.6M >= ZSZ/4
        if (idx < ZSZ/4)
            ((float4*)(zn + (size_t)g*ZSZ))[idx] = make_float4(0.f,0.f,0.f,0.f);
    }
}

// ---------------------------------------------------- semantic attention score
#define NPB 64
#define ZST 68
__global__ void __launch_bounds__(256) sa_score_k(SaP S) {
    extern __shared__ float sm[];
    float* W1sh = sm;                  // 8192
    float* zsh  = sm + DD*HH;          // 2*64*68
    float* b1sh = zsh + 2*NPB*ZST;     // 128
    float* w2sh = b1sh + HH;           // 128
    float* red  = w2sh + HH;           // 2

    int g = blockIdx.y, t = threadIdx.x;
    for (int i = t; i < DD*HH; i += 256) W1sh[i] = S.W1[g][i];
    if (t < HH) { b1sh[t] = S.b1[g][t]; w2sh[t] = S.w2[g][t]; }
    if (t < 2) red[t] = 0.f;

    int nb = blockIdx.x * NPB;
    const float4* base = (const float4*)(g_z + (size_t)(2*g)*ZSZ);
    for (int idx = t; idx < 2*NPB*16; idx += 256) {
        int p = idx >> 10;
        int n = (idx >> 4) & (NPB-1);
        int v = idx & 15;
        float4 val = make_float4(0.f,0.f,0.f,0.f);
        int gn = nb + n;
        if (gn < NN) val = __ldg(base + (size_t)p*(ZSZ/4) + (size_t)gn*16 + v);
        ((float4*)(zsh + (p*NPB + n)*ZST))[v] = val;
    }
    __syncthreads();

    int pair = t >> 3;
    int hq   = t & 7;
    ull acc[4][8];
    #pragma unroll
    for (int j = 0; j < 8; j++) {
        ull b = *(const ull*)(b1sh + 2*hq + 16*j);
        acc[0][j] = b; acc[1][j] = b; acc[2][j] = b; acc[3][j] = b;
    }

    const float* z0 = zsh + (pair*2)*ZST;
    const float* z1 = zsh + (NPB + pair*2)*ZST;
    for (int d = 0; d < DD; d++) {
        float a0 = z0[d], a1 = z0[ZST + d];
        float c0 = z1[d], c1 = z1[ZST + d];
        ull p0 = pack2(a0, a0), p1 = pack2(a1, a1);
        ull p2 = pack2(c0, c0), p3 = pack2(c1, c1);
        const float* wrow = W1sh + d*HH;
        #pragma unroll
        for (int j = 0; j < 8; j++) {
            ull w = *(const ull*)(wrow + 2*hq + 16*j);
            acc[0][j] = ffma2(p0, w, acc[0][j]);
            acc[1][j] = ffma2(p1, w, acc[1][j]);
            acc[2][j] = ffma2(p2, w, acc[2][j]);
            acc[3][j] = ffma2(p3, w, acc[3][j]);
        }
    }

    float part0 = 0.f, part1 = 0.f;
    #pragma unroll
    for (int r = 0; r < 4; r++) {
        int node = nb + pair*2 + (r & 1);
        if (node >= NN) continue;
        float sv = 0.f;
        #pragma unroll
        for (int j = 0; j < 8; j++) {
            float wa = w2sh[2*hq + 16*j], wb = w2sh[2*hq + 16*j + 1];
            float lo, hi; unpack2(acc[r][j], lo, hi);
            sv += tanha(lo)*wa + tanha(hi)*wb;
        }
        if (r < 2) part0 += sv; else part1 += sv;
    }
    #pragma unroll
    for (int o = 16; o; o >>= 1) {
        part0 += __shfl_down_sync(0xffffffffu, part0, o);
        part1 += __shfl_down_sync(0xffffffffu, part1, o);
    }
    if ((t & 31) == 0) { atomicAdd(&red[0], part0); atomicAdd(&red[1], part1); }
    __syncthreads();
    if (t == 0) {
        atomicAdd(g_wsum + 2*g,     red[0]);
        atomicAdd(g_wsum + 2*g + 1, red[1]);
    }
}

// ---------------------------------------------- combine (beta computed inline)
__global__ void combine_k(float* __restrict__ out) {
    __shared__ float bsh[8];
    int tt = threadIdx.x;
    if (tt == 0) {
        #pragma unroll
        for (int g = 0; g < 4; g++) {
            float w0 = g_wsum[2*g]   * (1.0f/NN);
            float w1 = g_wsum[2*g+1] * (1.0f/NN);
            float m = fmaxf(w0, w1);
            float e0 = __expf(w0-m), e1 = __expf(w1-m);
            float inv = 1.f/(e0+e1);
            bsh[2*g] = e0*inv; bsh[2*g+1] = e1*inv;
        }
    }
    __syncthreads();
    int t = blockIdx.x * blockDim.x + tt;
    const float4* Z = (const float4*)g_z;
    const size_t Pp = ZSZ/4;
    float4 r;
    if (t < NN*16) {
        float b0=bsh[0], b1=bsh[1], b4=bsh[4], b5=bsh[5];
        float4 x0=Z[t], x1=Z[Pp+t], x4=Z[4*Pp+t], x5=Z[5*Pp+t];
        r.x = b0*x0.x+b1*x1.x+b4*x4.x+b5*x5.x;
        r.y = b0*x0.y+b1*x1.y+b4*x4.y+b5*x5.y;
        r.z = b0*x0.z+b1*x1.z+b4*x4.z+b5*x5.z;
        r.w = b0*x0.w+b1*x1.w+b4*x4.w+b5*x5.w;
    } else {
        size_t u = t - NN*16;
        float b2=bsh[2], b3=bsh[3], b6=bsh[6], b7=bsh[7];
        float4 x2=Z[2*Pp+u], x3=Z[3*Pp+u], x6=Z[6*Pp+u], x7=Z[7*Pp+u];
        r.x = b2*x2.x+b3*x3.x+b6*x6.x+b7*x7.x;
        r.y = b2*x2.y+b3*x3.y+b6*x6.y+b7*x7.y;
        r.z = b2*x2.z+b3*x3.z+b6*x6.z+b7*x7.z;
        r.w = b2*x2.w+b3*x3.w+b6*x6.w+b7*x7.w;
    }
    ((float4*)out)[t] = r;
}

// ============================================================== host launcher
extern "C" void kernel_launch(void* const* d_in, const int* in_sizes, int n_in,
                              void* d_out, int out_size) {
    const float* feat_user = (const float*)d_in[0];
    const float* feat_item = (const float*)d_in[1];
    const float* attn_l    = (const float*)d_in[2];
    const float* attn_r    = (const float*)d_in[3];
    const float* W_gc      = (const float*)d_in[4];
    const float* b_gc      = (const float*)d_in[5];
    const float* sa_rel_W1 = (const float*)d_in[6];
    const float* sa_rel_b1 = (const float*)d_in[7];
    const float* sa_rel_w2 = (const float*)d_in[8];
    const float* sa_u_W1   = (const float*)d_in[9];
    const float* sa_u_b1   = (const float*)d_in[10];
    const float* sa_u_w2   = (const float*)d_in[11];
    const float* sa_i_W1   = (const float*)d_in[12];
    const float* sa_i_b1   = (const float*)d_in[13];
    const float* sa_i_w2   = (const float*)d_in[14];
    const int* rel_u_src   = (const int*)d_in[15];
    const int* rel_u_dst   = (const int*)d_in[16];
    const int* rel_i_src   = (const int*)d_in[17];
    const int* rel_i_dst   = (const int*)d_in[18];
    const int* mp_u_src    = (const int*)d_in[19];
    const int* mp_u_dst    = (const int*)d_in[20];
    const int* mp_i_src    = (const int*)d_in[21];
    const int* mp_i_dst    = (const int*)d_in[22];
    float* out = (float*)d_out;

    G4 C;
    C.s[0]=mp_u_src;    C.d[0]=mp_u_dst;
    C.s[1]=mp_u_src+EE; C.d[1]=mp_u_dst+EE;
    C.s[2]=mp_i_src;    C.d[2]=mp_i_dst;
    C.s[3]=mp_i_src+EE; C.d[3]=mp_i_dst+EE;
    SaP S;
    S.W1[0]=sa_rel_W1; S.b1[0]=sa_rel_b1; S.w2[0]=sa_rel_w2;
    S.W1[1]=sa_rel_W1; S.b1[1]=sa_rel_b1; S.w2[1]=sa_rel_w2;
    S.W1[2]=sa_u_W1;   S.b1[2]=sa_u_b1;   S.w2[2]=sa_u_w2;
    S.W1[3]=sa_i_W1;   S.b1[3]=sa_i_b1;   S.w2[3]=sa_i_w2;

    float* z_base;  float* s_base;  float* el_base;
    float* er_base; float* no_base; float* ni_base;
    cudaGetSymbolAddress((void**)&z_base,  g_z);
    cudaGetSymbolAddress((void**)&s_base,  g_s);
    cudaGetSymbolAddress((void**)&el_base, g_el);
    cudaGetSymbolAddress((void**)&er_base, g_er);
    cudaGetSymbolAddress((void**)&no_base, g_no);
    cudaGetSymbolAddress((void**)&ni_base, g_ni);

    const int TB = 256;
    const int SCAT_BLKS = (EE + EB - 1) / EB;   // 3907
    const int ZF4_BLKS  = ZSZ / 4 / TB;         // 3125

    // fused prologue: zero planes 0,1 + node arrays ; ler both tables ; degrees
    pre_k<<<dim3(6250, 4), TB>>>(z_base, feat_user, feat_item, attn_l, attn_r, C);

    // GAT pair 0: graphs 0,1 (rel_u, feat_item) -> planes 0,1 ; zero 2,3
    gat_scatter_k<<<dim3(SCAT_BLKS, 2), TB>>>(rel_u_src, rel_u_dst, feat_item,
                                              el_base, er_base, s_base, z_base);
    gat_final_zero_k<<<dim3(ZF4_BLKS, 2), TB>>>(s_base, z_base, z_base + (size_t)2*ZSZ);
    // GAT pair 1: graphs 2,3 (rel_i, feat_user) -> planes 2,3 ; zero 4,5
    gat_scatter_k<<<dim3(SCAT_BLKS, 2), TB>>>(rel_i_src, rel_i_dst, feat_user,
                                              el_base + 2*NN, er_base + 2*NN,
                                              s_base + 2*NN, z_base + (size_t)2*ZSZ);
    gat_final_zero_k<<<dim3(ZF4_BLKS, 2), TB>>>(s_base + 2*NN, z_base + (size_t)2*ZSZ,
                                                z_base + (size_t)4*ZSZ);

    // GC pair 0: graphs 0,1 (mp_u, feat_user) -> planes 4,5 ; zero 6,7
    gc_scatter_k<<<dim3(SCAT_BLKS, 2), TB>>>(mp_u_src, mp_u_dst, feat_user,
                                             no_base, z_base + (size_t)4*ZSZ);
    gc_gemm_zero_k<<<dim3(NN/8, 2), TB>>>(z_base + (size_t)4*ZSZ, W_gc, b_gc,
                                          ni_base, z_base + (size_t)6*ZSZ);
    // GC pair 1: graphs 2,3 (mp_i, feat_item) -> planes 6,7
    gc_scatter_k<<<dim3(SCAT_BLKS, 2), TB>>>(mp_i_src, mp_i_dst, feat_item,
                                             no_base + 2*NN, z_base + (size_t)6*ZSZ);
    gc_gemm_zero_k<<<dim3(NN/8, 2), TB>>>(z_base + (size_t)6*ZSZ, W_gc + 2*DD*DD,
                                          b_gc + 2*DD, ni_base + 2*NN, nullptr);

    int sa_smem = (DD*HH + 2*NPB*ZST + HH + HH + 2) * sizeof(float);
    cudaFuncSetAttribute(sa_score_k, cudaFuncAttributeMaxDynamicSharedMemorySize, sa_smem);
    sa_score_k<<<dim3((NN + NPB - 1)/NPB, 4), TB, sa_smem>>>(S);

    combine_k<<<2*NN*16/TB, TB>>>(out);
}